// round 1
// baseline (speedup 1.0000x reference)
#include <cuda_runtime.h>
#include <math.h>

// Problem constants
#define NGv 12
#define Bv  8
#define Sv  1280
#define Cv  512     // NFG == NFR == 512

// ---------------- device scratch (no allocations allowed) ----------------
__device__ float  g_theta[Bv * Sv * Cv];          // 21 MB
__device__ float  g_phi  [Bv * Sv * Cv];          // 21 MB
__device__ float  g_sim  [Bv * Sv * Sv];          // 52 MB (attn written in-place)
__device__ float  g_tmp  [Bv * Sv * Cv];          // 21 MB
__device__ float  g_agg  [Bv * Sv * Cv];          // 21 MB
__device__ float  g_cx[Bv * Sv], g_cy[Bv * Sv], g_rr[Bv * Sv];
__device__ double g_stats[Bv * 2];                // sum, sumsq per batch
__device__ float  g_mu[Bv], g_rstd[Bv];

// ---------------- batched SGEMM: C = alpha * A @ op(B) + bias ----------------
// A: [M,K] row-major. TRB=false: B [K,N] row-major. TRB=true: B [N,K] row-major.
// 128x128 tile, BK=8, 256 threads, 8x8 per thread.
#define BM 128
#define BN 128
#define BK 8
#define TM 8
#define TN 8

template <bool TRB>
__global__ __launch_bounds__(256, 2)
void sgemm_kernel(const float* __restrict__ A, const float* __restrict__ Bm,
                  const float* __restrict__ bias, float* __restrict__ C,
                  int M, int N, int K,
                  size_t strideA, size_t strideB, size_t strideC, float alpha)
{
    const int bz = blockIdx.z;
    A  += (size_t)bz * strideA;
    Bm += (size_t)bz * strideB;
    C  += (size_t)bz * strideC;

    __shared__ float As[BK][BM];
    __shared__ float Bs[BK][BN];

    const int tid = threadIdx.x;
    const int row0 = blockIdx.y * BM;
    const int col0 = blockIdx.x * BN;
    const int tx = tid & 15;       // 16 thread cols
    const int ty = tid >> 4;       // 16 thread rows

    // A tile load: 128x8 = 256 float4, one per thread
    const int arow = tid >> 1;
    const int acol = (tid & 1) * 4;
    // B tile load (NN): 8x128; (NT): 128x8
    const int bnrow = tid >> 5;              // 0..7  (k)
    const int bncol = (tid & 31) * 4;        // 0..124 (n)
    const int btrow = tid >> 1;              // 0..127 (n)
    const int btcol = (tid & 1) * 4;         // 0 or 4 (k)

    float acc[TM][TN];
    #pragma unroll
    for (int i = 0; i < TM; i++)
        #pragma unroll
        for (int j = 0; j < TN; j++) acc[i][j] = 0.f;

    for (int k0 = 0; k0 < K; k0 += BK) {
        float4 a4 = *(const float4*)(A + (size_t)(row0 + arow) * K + k0 + acol);
        As[acol + 0][arow] = a4.x;
        As[acol + 1][arow] = a4.y;
        As[acol + 2][arow] = a4.z;
        As[acol + 3][arow] = a4.w;
        if (!TRB) {
            float4 b4 = *(const float4*)(Bm + (size_t)(k0 + bnrow) * N + col0 + bncol);
            *(float4*)&Bs[bnrow][bncol] = b4;
        } else {
            float4 b4 = *(const float4*)(Bm + (size_t)(col0 + btrow) * K + k0 + btcol);
            Bs[btcol + 0][btrow] = b4.x;
            Bs[btcol + 1][btrow] = b4.y;
            Bs[btcol + 2][btrow] = b4.z;
            Bs[btcol + 3][btrow] = b4.w;
        }
        __syncthreads();

        #pragma unroll
        for (int kk = 0; kk < BK; kk++) {
            float4 a0 = *(const float4*)&As[kk][ty * TM];
            float4 a1 = *(const float4*)&As[kk][ty * TM + 4];
            float4 b0 = *(const float4*)&Bs[kk][tx * TN];
            float4 b1 = *(const float4*)&Bs[kk][tx * TN + 4];
            float ar[TM] = {a0.x, a0.y, a0.z, a0.w, a1.x, a1.y, a1.z, a1.w};
            float br[TN] = {b0.x, b0.y, b0.z, b0.w, b1.x, b1.y, b1.z, b1.w};
            #pragma unroll
            for (int i = 0; i < TM; i++)
                #pragma unroll
                for (int j = 0; j < TN; j++)
                    acc[i][j] += ar[i] * br[j];
        }
        __syncthreads();
    }

    #pragma unroll
    for (int i = 0; i < TM; i++) {
        size_t roff = (size_t)(row0 + ty * TM + i) * N + col0 + tx * TN;
        #pragma unroll
        for (int j = 0; j < TN; j += 4) {
            float4 o;
            float b0 = bias ? bias[col0 + tx * TN + j + 0] : 0.f;
            float b1 = bias ? bias[col0 + tx * TN + j + 1] : 0.f;
            float b2 = bias ? bias[col0 + tx * TN + j + 2] : 0.f;
            float b3 = bias ? bias[col0 + tx * TN + j + 3] : 0.f;
            o.x = acc[i][j + 0] * alpha + b0;
            o.y = acc[i][j + 1] * alpha + b1;
            o.z = acc[i][j + 2] * alpha + b2;
            o.w = acc[i][j + 3] * alpha + b3;
            *(float4*)(C + roff + j) = o;
        }
    }
}

// ---------------- box centers ----------------
__global__ void pos_kernel(const float* __restrict__ box)
{
    int idx = blockIdx.x * blockDim.x + threadIdx.x;
    if (idx >= Bv * Sv) return;
    float x0 = box[idx * 4 + 0];
    float y0 = box[idx * 4 + 1];
    float x1 = box[idx * 4 + 2];
    float y1 = box[idx * 4 + 3];
    float cx = (x0 + x1) * 0.5f;
    float cy = (y0 + y1) * 0.5f;
    g_cx[idx] = cx;
    g_cy[idx] = cy;
    g_rr[idx] = cx * cx + cy * cy;
}

// ---------------- masked softmax over rows (mask computed on the fly) ----------------
__global__ __launch_bounds__(256)
void masked_softmax_kernel(const float* __restrict__ sim, float* __restrict__ attn,
                           const void* __restrict__ owp)
{
    const int row = blockIdx.x;        // b*S + n
    const int b = row / Sv;
    const int tid = threadIdx.x;
    const float* srow = sim + (size_t)row * Sv;
    float* orow = attn + (size_t)row * Sv;

    float ow = 224.0f;
    if (owp) {
        int vi = *(const int*)owp;
        ow = (vi > 0 && vi < 1000000) ? (float)vi : __int_as_float(vi);
    }
    const float thr = 0.2f * ow;
    const float thr2 = thr * thr;

    const float rn = g_rr[row], cxn = g_cx[row], cyn = g_cy[row];
    const float* cxb = g_cx + b * Sv;
    const float* cyb = g_cy + b * Sv;
    const float* rb  = g_rr + b * Sv;

    float v[5];
    float mx = -INFINITY;
    #pragma unroll
    for (int u = 0; u < 5; u++) {
        int m = tid + u * 256;
        float d2 = (rn - 2.0f * (cxn * cxb[m] + cyn * cyb[m])) + rb[m];
        float s = srow[m];
        v[u] = (d2 > thr2) ? -INFINITY : s;
        mx = fmaxf(mx, v[u]);
    }

    __shared__ float sh[8];
    #pragma unroll
    for (int o = 16; o > 0; o >>= 1) mx = fmaxf(mx, __shfl_xor_sync(0xffffffffu, mx, o));
    if ((tid & 31) == 0) sh[tid >> 5] = mx;
    __syncthreads();
    if (tid < 32) {
        float t = (tid < 8) ? sh[tid] : -INFINITY;
        #pragma unroll
        for (int o = 4; o > 0; o >>= 1) t = fmaxf(t, __shfl_xor_sync(0xffffffffu, t, o));
        if (tid == 0) sh[0] = t;
    }
    __syncthreads();
    mx = sh[0];
    __syncthreads();

    float sum = 0.f;
    #pragma unroll
    for (int u = 0; u < 5; u++) {
        float e = __expf(v[u] - mx);
        v[u] = e;
        sum += e;
    }
    #pragma unroll
    for (int o = 16; o > 0; o >>= 1) sum += __shfl_xor_sync(0xffffffffu, sum, o);
    if ((tid & 31) == 0) sh[tid >> 5] = sum;
    __syncthreads();
    if (tid < 32) {
        float t = (tid < 8) ? sh[tid] : 0.f;
        #pragma unroll
        for (int o = 4; o > 0; o >>= 1) t += __shfl_xor_sync(0xffffffffu, t, o);
        if (tid == 0) sh[0] = t;
    }
    __syncthreads();
    const float inv = 1.0f / sh[0];
    #pragma unroll
    for (int u = 0; u < 5; u++) orow[tid + u * 256] = v[u] * inv;
}

// ---------------- LayerNorm statistics ----------------
__global__ void zero_stats_kernel()
{
    int i = threadIdx.x;
    if (i < Bv * 2) g_stats[i] = 0.0;
}

__global__ __launch_bounds__(256)
void reduce_stats_kernel(const float* __restrict__ agg)
{
    const int b = blockIdx.y;
    const float* p = agg + (size_t)b * Sv * Cv;
    double s = 0.0, q = 0.0;
    for (int i = blockIdx.x * blockDim.x + threadIdx.x; i < Sv * Cv; i += gridDim.x * blockDim.x) {
        float v = p[i];
        s += (double)v;
        q += (double)v * (double)v;
    }
    #pragma unroll
    for (int o = 16; o > 0; o >>= 1) {
        s += __shfl_xor_sync(0xffffffffu, s, o);
        q += __shfl_xor_sync(0xffffffffu, q, o);
    }
    __shared__ double shs[8], shq[8];
    const int tid = threadIdx.x;
    if ((tid & 31) == 0) { shs[tid >> 5] = s; shq[tid >> 5] = q; }
    __syncthreads();
    if (tid == 0) {
        for (int w = 1; w < 8; w++) { s += shs[w]; q += shq[w]; }
        atomicAdd(&g_stats[b * 2 + 0], s);
        atomicAdd(&g_stats[b * 2 + 1], q);
    }
}

__global__ void mustd_kernel()
{
    int b = threadIdx.x;
    if (b < Bv) {
        const double n = (double)Sv * (double)Cv;
        double mu = g_stats[b * 2 + 0] / n;
        double var = g_stats[b * 2 + 1] / n - mu * mu;
        g_mu[b] = (float)mu;
        g_rstd[b] = rsqrtf((float)var + 1e-5f);
    }
}

// ---------------- out += relu(LN(agg)*scale + bias) ----------------
__global__ __launch_bounds__(256)
void finalize_kernel(const float* __restrict__ agg, const float* __restrict__ lns,
                     const float* __restrict__ lnb, float* __restrict__ out, int accumulate)
{
    size_t idx = (size_t)blockIdx.x * blockDim.x + threadIdx.x;
    if (idx >= (size_t)Bv * Sv * Cv) return;
    int b = (int)(idx / ((size_t)Sv * Cv));
    int j = (int)(idx % ((size_t)Sv * Cv));
    float mu = g_mu[b];
    float rstd = g_rstd[b];
    float v = (agg[idx] - mu) * rstd * lns[j] + lnb[j];
    v = fmaxf(v, 0.f);
    out[idx] = accumulate ? out[idx] + v : v;
}

// ---------------- launch ----------------
extern "C" void kernel_launch(void* const* d_in, const int* in_sizes, int n_in,
                              void* d_out, int out_size)
{
    const float* x   = (const float*)d_in[0];   // [B,S,C]
    const float* box = (const float*)d_in[1];   // [B*S,4]
    const float* Wt  = (const float*)d_in[2];   // [NG,C,C]
    const float* bt  = (const float*)d_in[3];   // [NG,C]
    const float* Wp  = (const float*)d_in[4];
    const float* bp  = (const float*)d_in[5];
    const float* Wg  = (const float*)d_in[6];   // [NG,C,C]
    const float* lns = (const float*)d_in[7];   // [NG,S,C]
    const float* lnb = (const float*)d_in[8];   // [NG,S,C]
    const void*  owp = (n_in > 10) ? d_in[10] : nullptr;   // OW scalar

    float* out = (float*)d_out;                               // [B,S,C]
    float* rel = out + (size_t)Bv * Sv * Cv;                  // [B,S,S]

    float *theta, *phi, *sim, *tmp, *agg;
    cudaGetSymbolAddress((void**)&theta, g_theta);
    cudaGetSymbolAddress((void**)&phi,   g_phi);
    cudaGetSymbolAddress((void**)&sim,   g_sim);
    cudaGetSymbolAddress((void**)&tmp,   g_tmp);
    cudaGetSymbolAddress((void**)&agg,   g_agg);

    const size_t sSC = (size_t)Sv * Cv;   // batch stride [S,C]
    const size_t sSS = (size_t)Sv * Sv;   // batch stride [S,S]
    const float inv_sqrt = 0.04419417382415922f;   // 1/sqrt(512)

    pos_kernel<<<(Bv * Sv + 255) / 256, 256>>>(box);

    for (int i = 0; i < NGv; i++) {
        const float* Wti = Wt + (size_t)i * Cv * Cv;
        const float* Wpi = Wp + (size_t)i * Cv * Cv;
        const float* Wgi = Wg + (size_t)i * Cv * Cv;
        const float* bti = bt + (size_t)i * Cv;
        const float* bpi = bp + (size_t)i * Cv;
        const float* lnsi = lns + (size_t)i * sSC;
        const float* lnbi = lnb + (size_t)i * sSC;

        // theta = x @ W_theta[i] + b_theta[i]   [B] x [S,C]@[C,C]
        {
            dim3 grid(Cv / BN, Sv / BM, Bv);
            sgemm_kernel<false><<<grid, 256>>>(x, Wti, bti, theta, Sv, Cv, Cv, sSC, 0, sSC, 1.0f);
            sgemm_kernel<false><<<grid, 256>>>(x, Wpi, bpi, phi,   Sv, Cv, Cv, sSC, 0, sSC, 1.0f);
        }
        // sim = theta @ phi^T * inv_sqrt        [S,S]
        {
            dim3 grid(Sv / BN, Sv / BM, Bv);
            sgemm_kernel<true><<<grid, 256>>>(theta, phi, nullptr, sim, Sv, Sv, Cv, sSC, sSC, sSS, inv_sqrt);
        }
        // masked softmax; last iteration writes relation_graph straight to output
        float* attn = (i == NGv - 1) ? rel : sim;
        masked_softmax_kernel<<<Bv * Sv, 256>>>(sim, attn, owp);
        // tmp = attn @ x                        [S,S]@[S,C]
        {
            dim3 grid(Cv / BN, Sv / BM, Bv);
            sgemm_kernel<false><<<grid, 256>>>(attn, x, nullptr, tmp, Sv, Cv, Sv, sSS, sSC, sSC, 1.0f);
        }
        // agg = tmp @ W_gcn[i]
        {
            dim3 grid(Cv / BN, Sv / BM, Bv);
            sgemm_kernel<false><<<grid, 256>>>(tmp, Wgi, nullptr, agg, Sv, Cv, Cv, sSC, 0, sSC, 1.0f);
        }
        // LayerNorm over [S,C] per batch, then out += relu(...)
        zero_stats_kernel<<<1, 32>>>();
        {
            dim3 grid(64, Bv);
            reduce_stats_kernel<<<grid, 256>>>(agg);
        }
        mustd_kernel<<<1, 32>>>();
        {
            int nblk = (int)(((size_t)Bv * Sv * Cv + 255) / 256);
            finalize_kernel<<<nblk, 256>>>(agg, lnsi, lnbi, out, i == 0 ? 0 : 1);
        }
    }
}

// round 5
// speedup vs baseline: 3.6794x; 3.6794x over previous
#include <cuda_runtime.h>
#include <math.h>
#include <stdint.h>

#define NGv 12
#define Bv  8
#define Sv  1280
#define Cv  512

// ---------------- device scratch ----------------
__device__ float g_xh [Bv*Sv*Cv], g_xl [Bv*Sv*Cv];     // x hi/lo [B,S,C]
__device__ float g_xth[Bv*Cv*Sv], g_xtl[Bv*Cv*Sv];     // x^T hi/lo [B,C,S]
__device__ float g_wth[NGv*Cv*Cv], g_wtl[NGv*Cv*Cv];   // W_theta^T hi/lo [NG,n,k]
__device__ float g_wph[NGv*Cv*Cv], g_wpl[NGv*Cv*Cv];
__device__ float g_wgh[NGv*Cv*Cv], g_wgl[NGv*Cv*Cv];
__device__ float g_thh[Bv*Sv*Cv], g_thl[Bv*Sv*Cv];     // theta hi/lo
__device__ float g_phh[Bv*Sv*Cv], g_phl[Bv*Sv*Cv];     // phi hi/lo
__device__ float g_sim[Bv*Sv*Sv];                      // sim fp32
__device__ float g_ath[Bv*Sv*Sv], g_atl[Bv*Sv*Sv];     // attn hi/lo
__device__ float g_tph[Bv*Sv*Cv], g_tpl[Bv*Sv*Cv];     // tmp hi/lo
__device__ float g_agg[Bv*Sv*Cv];
__device__ float g_cx[Bv*Sv], g_cy[Bv*Sv], g_rr[Bv*Sv];
__device__ double g_stats[Bv*2];
__device__ float g_mu[Bv], g_rstd[Bv];

// ---------------- PTX helpers ----------------
__device__ __forceinline__ uint32_t sm2u(const void* p) {
    uint32_t a;
    asm("{ .reg .u64 t; cvta.to.shared.u64 t, %1; cvt.u32.u64 %0, t; }" : "=r"(a) : "l"(p));
    return a;
}
#define SWZ(o) ((o) ^ (((o) >> 3) & 0x70u))

__device__ __forceinline__ float tf32r(float x) {
    uint32_t u;
    asm("cvt.rna.tf32.f32 %0, %1;" : "=r"(u) : "f"(x));
    return __uint_as_float(u);
}

__device__ __forceinline__ void cpasync16(uint32_t dst, const void* src) {
    asm volatile("cp.async.cg.shared.global [%0], [%1], 16;" :: "r"(dst), "l"(src));
}
// NOTE: .noinc is load-bearing. The default (inc) form self-balances the
// mbarrier (pend-count +1 then -1) and never satisfies the base count ->
// full-barrier never flips -> R4's deadlock/timeout.
__device__ __forceinline__ void cpasync_arrive_noinc(uint32_t bar) {
    asm volatile("cp.async.mbarrier.arrive.noinc.shared.b64 [%0];" :: "r"(bar));
}
__device__ __forceinline__ void mbar_init(uint32_t bar, uint32_t cnt) {
    asm volatile("mbarrier.init.shared.b64 [%0], %1;" :: "r"(bar), "r"(cnt) : "memory");
}
__device__ __forceinline__ void mbar_wait(uint32_t bar, uint32_t parity) {
    asm volatile(
        "{\n\t"
        ".reg .pred P;\n\t"
        "WL%=:\n\t"
        "mbarrier.try_wait.parity.acquire.cta.shared::cta.b64 P, [%0], %1;\n\t"
        "@P bra WD%=;\n\t"
        "bra WL%=;\n\t"
        "WD%=:\n\t"
        "}"
        :: "r"(bar), "r"(parity) : "memory");
}
__device__ __forceinline__ void fence_proxy_async_cta() {
    asm volatile("fence.proxy.async.shared::cta;" ::: "memory");
}

#if defined(__CUDA_ARCH_FEAT_SM103_ALL) || !defined(__CUDA_ARCH__)
#define HAS_TCGEN05 1
#else
#define HAS_TCGEN05 0
#endif

#if HAS_TCGEN05
__device__ __forceinline__ void tc_commit(uint32_t bar) {
    asm volatile("tcgen05.commit.cta_group::1.mbarrier::arrive::one.shared::cluster.b64 [%0];"
                 :: "r"(bar) : "memory");
}
__device__ __forceinline__ void mma_tf32(uint32_t d, uint64_t ad, uint64_t bd, uint32_t idesc, bool acc) {
    uint32_t e = acc ? 1u : 0u;
    asm volatile(
        "{\n\t"
        ".reg .pred p;\n\t"
        "setp.ne.u32 p, %4, 0;\n\t"
        "tcgen05.mma.cta_group::1.kind::tf32 [%0], %1, %2, %3, p;\n\t"
        "}"
        :: "r"(d), "l"(ad), "l"(bd), "r"(idesc), "r"(e) : "memory");
}
#define TC_ALLOC(smemaddr, n) \
    asm volatile("tcgen05.alloc.cta_group::1.sync.aligned.shared::cta.b32 [%0], %1;" \
                 :: "r"(smemaddr), "r"((uint32_t)(n)) : "memory")
#define TC_RELINQ() \
    asm volatile("tcgen05.relinquish_alloc_permit.cta_group::1.sync.aligned;")
#define TC_DEALLOC(tm, n) \
    asm volatile("tcgen05.dealloc.cta_group::1.sync.aligned.b32 %0, %1;" :: "r"(tm), "r"((uint32_t)(n)))
#define TC_FENCE_AFTER()  asm volatile("tcgen05.fence::after_thread_sync;" ::: "memory")
#define TC_WAIT_LD()      asm volatile("tcgen05.wait::ld.sync.aligned;" ::: "memory")
#define LDTM32(r, a) \
    asm volatile( \
        "tcgen05.ld.sync.aligned.32x32b.x32.b32 " \
        "{%0, %1, %2, %3, %4, %5, %6, %7, " \
        " %8, %9, %10, %11, %12, %13, %14, %15, " \
        " %16, %17, %18, %19, %20, %21, %22, %23, " \
        " %24, %25, %26, %27, %28, %29, %30, %31}, [%32];" \
        : "=r"((r)[0]),  "=r"((r)[1]),  "=r"((r)[2]),  "=r"((r)[3]), \
          "=r"((r)[4]),  "=r"((r)[5]),  "=r"((r)[6]),  "=r"((r)[7]), \
          "=r"((r)[8]),  "=r"((r)[9]),  "=r"((r)[10]), "=r"((r)[11]), \
          "=r"((r)[12]), "=r"((r)[13]), "=r"((r)[14]), "=r"((r)[15]), \
          "=r"((r)[16]), "=r"((r)[17]), "=r"((r)[18]), "=r"((r)[19]), \
          "=r"((r)[20]), "=r"((r)[21]), "=r"((r)[22]), "=r"((r)[23]), \
          "=r"((r)[24]), "=r"((r)[25]), "=r"((r)[26]), "=r"((r)[27]), \
          "=r"((r)[28]), "=r"((r)[29]), "=r"((r)[30]), "=r"((r)[31]) \
        : "r"(a))
#endif

static constexpr uint64_t DESC_BASE =
    (2ull << 61) | (1ull << 46) | (64ull << 32) | (1ull << 16);   // SW128, Blackwell, SBO=64, LBO=1
__device__ __forceinline__ uint64_t mk_desc(uint32_t addr) {
    return DESC_BASE | ((uint64_t)(addr >> 4) & 0x3FFFull);
}

// idesc: dtype=F32(1<<4), atype=TF32(2<<7), btype=TF32(2<<10), N=256 (32<<17), M=128 (8<<24)
static constexpr uint32_t IDESC = (1u << 4) | (2u << 7) | (2u << 10) | (32u << 17) | (8u << 24);

// ---------------- tcgen05 3xTF32 GEMM: D = alpha*(A @ B^T) + bias ----------------
// A[M,K] K-major (hi/lo), B[N,K] K-major (hi/lo). Tile 128x256, K-chunk 32.
// outF -> fp32 store; outH/outL -> tf32 hi/lo split store.
#define KC 32
#define STG_BYTES 98304          // 96KB per stage (Ah 16K | Al 16K | Bh 32K | Bl 32K)
#define OFF_AL 16384
#define OFF_BH 32768
#define OFF_BL 65536
#define DYN_BYTES 196608

__global__ __launch_bounds__(160, 1)
void tcgemm(const float* __restrict__ Ah, const float* __restrict__ Al, size_t sAz, int ldA,
            const float* __restrict__ Bh, const float* __restrict__ Bl,
            const float* __restrict__ Bh2, const float* __restrict__ Bl2, size_t sBz, int ldB,
            float* outF, float* outH, float* outL, float* outH2, float* outL2,
            size_t sOz, int ldO,
            const float* bias, const float* bias2, float alpha, int K, int zsplit)
{
#if HAS_TCGEN05
    extern __shared__ __align__(1024) char dynsm[];
    __shared__ __align__(8) uint64_t s_full[2], s_empty[2], s_done;
    __shared__ uint32_t s_tptr;

    const int tid = threadIdx.x;
    const int wid = tid >> 5;
    const int lane = tid & 31;

    int z = blockIdx.z;
    if (z >= zsplit) { z -= zsplit; Bh = Bh2; Bl = Bl2; outH = outH2; outL = outL2; bias = bias2; }
    const int m0   = blockIdx.y * 128;
    const int col0 = blockIdx.x * 256;

    const uint32_t dynu = sm2u(dynsm);
    uint32_t fullb[2]  = { sm2u(&s_full[0]),  sm2u(&s_full[1])  };
    uint32_t emptyb[2] = { sm2u(&s_empty[0]), sm2u(&s_empty[1]) };
    const uint32_t doneb = sm2u(&s_done);

    if (tid == 0) {
        mbar_init(fullb[0], 128); mbar_init(fullb[1], 128);
        mbar_init(emptyb[0], 1);  mbar_init(emptyb[1], 1);
        mbar_init(doneb, 1);
    }
    __syncthreads();
    if (wid == 4) {
        TC_ALLOC(sm2u(&s_tptr), 256);
        TC_RELINQ();
    }
    __syncthreads();
    const uint32_t tmem = s_tptr;

    const int nk = K / KC;

    if (wid < 4) {
        // ---- producers (128 threads) ----
        const float* aH = Ah + (size_t)z * sAz + (size_t)m0 * ldA;
        const float* aL = Al + (size_t)z * sAz + (size_t)m0 * ldA;
        const float* bH = Bh + (size_t)z * sBz + (size_t)col0 * ldB;
        const float* bL = Bl + (size_t)z * sBz + (size_t)col0 * ldB;
        int st = 0, ph = 1;
        for (int c = 0; c < nk; c++) {
            mbar_wait(emptyb[st], ph);
            const uint32_t sb = dynu + st * STG_BYTES;
            const int k0 = c * KC;
            #pragma unroll
            for (int i = 0; i < 8; i++) {
                int idx = i * 128 + tid;
                int r = idx >> 3, cc = idx & 7;
                uint32_t so = SWZ((uint32_t)(r * 128 + cc * 16));
                const size_t go = (size_t)r * ldA + k0 + cc * 4;
                cpasync16(sb + so, aH + go);
                cpasync16(sb + OFF_AL + so, aL + go);
            }
            #pragma unroll
            for (int i = 0; i < 16; i++) {
                int idx = i * 128 + tid;
                int r = idx >> 3, cc = idx & 7;
                uint32_t so = SWZ((uint32_t)(r * 128 + cc * 16));
                const size_t go = (size_t)r * ldB + k0 + cc * 4;
                cpasync16(sb + OFF_BH + so, bH + go);
                cpasync16(sb + OFF_BL + so, bL + go);
            }
            cpasync_arrive_noinc(fullb[st]);
            if (++st == 2) { st = 0; ph ^= 1; }
        }
    } else if (lane == 0) {
        // ---- MMA issuer (1 thread) ----
        int st = 0, ph = 0;
        for (int c = 0; c < nk; c++) {
            mbar_wait(fullb[st], ph);
            fence_proxy_async_cta();    // generic-proxy cp.async writes -> async-proxy MMA reads
            const uint32_t sb = dynu + st * STG_BYTES;
            uint64_t dah = mk_desc(sb),          dal = mk_desc(sb + OFF_AL);
            uint64_t dbh = mk_desc(sb + OFF_BH), dbl = mk_desc(sb + OFF_BL);
            #pragma unroll
            for (int ks = 0; ks < 4; ks++)
                mma_tf32(tmem, dah + ks * 2, dbh + ks * 2, IDESC, !(c == 0 && ks == 0));
            #pragma unroll
            for (int ks = 0; ks < 4; ks++)
                mma_tf32(tmem, dah + ks * 2, dbl + ks * 2, IDESC, true);
            #pragma unroll
            for (int ks = 0; ks < 4; ks++)
                mma_tf32(tmem, dal + ks * 2, dbh + ks * 2, IDESC, true);
            tc_commit(emptyb[st]);
            if (++st == 2) { st = 0; ph ^= 1; }
        }
        tc_commit(doneb);
    }

    // ---- all threads: wait for every MMA, then epilogue ----
    mbar_wait(doneb, 0);
    TC_FENCE_AFTER();

    if (wid < 4) {
        float* tile = (float*)(dynsm + wid * 4352);     // 32x33 floats per warp
        const size_t obase = (size_t)z * sOz;
        for (int c0 = 0; c0 < 256; c0 += 32) {
            uint32_t regs[32];
            LDTM32(regs, tmem + c0);
            TC_WAIT_LD();
            #pragma unroll
            for (int j = 0; j < 32; j++) {
                float v = __uint_as_float(regs[j]) * alpha;
                if (bias) v += bias[col0 + c0 + j];
                tile[lane * 33 + j] = v;
            }
            __syncwarp();
            #pragma unroll
            for (int i = 0; i < 8; i++) {
                int f = i * 32 + lane;
                int rr = f >> 3, q = (f & 7) * 4;
                float4 v4;
                v4.x = tile[rr * 33 + q + 0];
                v4.y = tile[rr * 33 + q + 1];
                v4.z = tile[rr * 33 + q + 2];
                v4.w = tile[rr * 33 + q + 3];
                size_t off = obase + (size_t)(m0 + wid * 32 + rr) * ldO + col0 + c0 + q;
                if (outF) *(float4*)(outF + off) = v4;
                if (outH) {
                    float4 h, l;
                    h.x = tf32r(v4.x); l.x = tf32r(v4.x - h.x);
                    h.y = tf32r(v4.y); l.y = tf32r(v4.y - h.y);
                    h.z = tf32r(v4.z); l.z = tf32r(v4.z - h.z);
                    h.w = tf32r(v4.w); l.w = tf32r(v4.w - h.w);
                    *(float4*)(outH + off) = h;
                    *(float4*)(outL + off) = l;
                }
            }
            __syncwarp();
        }
    }
    __syncthreads();
    if (wid == 4) TC_DEALLOC(tmem, 256);
#else
    // -------- plain-sm_103 fallback (insurance for the non-'a' gencode pass) --------
    int z = blockIdx.z;
    if (z >= zsplit) { z -= zsplit; Bh = Bh2; Bl = Bl2; outH = outH2; outL = outL2; bias = bias2; }
    const int m0   = blockIdx.y * 128;
    const int col0 = blockIdx.x * 256;
    const float* aH = Ah + (size_t)z * sAz;
    const float* aL = Al + (size_t)z * sAz;
    const float* bH = Bh + (size_t)z * sBz;
    const float* bL = Bl + (size_t)z * sBz;
    for (int idx = threadIdx.x; idx < 128 * 256; idx += blockDim.x) {
        int mi = m0 + (idx >> 8);
        int ni = col0 + (idx & 255);
        const float* pa  = aH + (size_t)mi * ldA;
        const float* pa2 = aL + (size_t)mi * ldA;
        const float* pb  = bH + (size_t)ni * ldB;
        const float* pb2 = bL + (size_t)ni * ldB;
        float s = 0.f;
        for (int k = 0; k < K; k++)
            s += (pa[k] + pa2[k]) * (pb[k] + pb2[k]);
        float v = s * alpha + (bias ? bias[ni] : 0.f);
        size_t off = (size_t)z * sOz + (size_t)mi * ldO + ni;
        if (outF) outF[off] = v;
        if (outH) {
            float h = tf32r(v);
            outH[off] = h;
            outL[off] = tf32r(v - h);
        }
    }
#endif
}

// ---------------- transpose + tf32 hi/lo split ----------------
__global__ void conv_t_kernel(const float* __restrict__ in, float* __restrict__ th,
                              float* __restrict__ tl, float* sh, float* sl, int R, int Cc)
{
    __shared__ float t[32][33];
    const int z = blockIdx.z;
    const size_t zb = (size_t)z * R * Cc;
    const int r0 = blockIdx.y * 32, c0 = blockIdx.x * 32;
    #pragma unroll
    for (int k = 0; k < 4; k++) {
        int r = r0 + threadIdx.y + k * 8;
        size_t idx = zb + (size_t)r * Cc + c0 + threadIdx.x;
        float v = in[idx];
        t[threadIdx.y + k * 8][threadIdx.x] = v;
        if (sh) {
            float hi = tf32r(v);
            sh[idx] = hi;
            sl[idx] = tf32r(v - hi);
        }
    }
    __syncthreads();
    #pragma unroll
    for (int k = 0; k < 4; k++) {
        int cc = c0 + threadIdx.y + k * 8;
        int rr = r0 + threadIdx.x;
        float v = t[threadIdx.x][threadIdx.y + k * 8];
        size_t o = zb + (size_t)cc * R + rr;
        float hi = tf32r(v);
        th[o] = hi;
        tl[o] = tf32r(v - hi);
    }
}

// ---------------- box centers ----------------
__global__ void pos_kernel(const float* __restrict__ box)
{
    int idx = blockIdx.x * blockDim.x + threadIdx.x;
    if (idx >= Bv * Sv) return;
    float cx = (box[idx * 4 + 0] + box[idx * 4 + 2]) * 0.5f;
    float cy = (box[idx * 4 + 1] + box[idx * 4 + 3]) * 0.5f;
    g_cx[idx] = cx; g_cy[idx] = cy; g_rr[idx] = cx * cx + cy * cy;
}

// ---------------- masked softmax (mask on the fly), emits hi/lo (+optional fp32) -------
__global__ __launch_bounds__(256)
void masked_softmax_kernel(const float* __restrict__ sim, float* __restrict__ aH,
                           float* __restrict__ aL, float* relF, const void* __restrict__ owp)
{
    const int row = blockIdx.x;
    const int b = row / Sv;
    const int tid = threadIdx.x;
    const float* srow = sim + (size_t)row * Sv;

    float ow = 224.0f;
    if (owp) {
        int vi = *(const int*)owp;
        ow = (vi > 0 && vi < 1000000) ? (float)vi : __int_as_float(vi);
    }
    const float thr2 = (0.2f * ow) * (0.2f * ow);

    const float rn = g_rr[row], cxn = g_cx[row], cyn = g_cy[row];
    const float* cxb = g_cx + b * Sv;
    const float* cyb = g_cy + b * Sv;
    const float* rb  = g_rr + b * Sv;

    float v[5];
    float mx = -INFINITY;
    #pragma unroll
    for (int u = 0; u < 5; u++) {
        int m = tid + u * 256;
        float d2 = (rn - 2.0f * (cxn * cxb[m] + cyn * cyb[m])) + rb[m];
        v[u] = (d2 > thr2) ? -INFINITY : srow[m];
        mx = fmaxf(mx, v[u]);
    }

    __shared__ float sh[8];
    #pragma unroll
    for (int o = 16; o > 0; o >>= 1) mx = fmaxf(mx, __shfl_xor_sync(0xffffffffu, mx, o));
    if ((tid & 31) == 0) sh[tid >> 5] = mx;
    __syncthreads();
    if (tid < 32) {
        float t = (tid < 8) ? sh[tid] : -INFINITY;
        #pragma unroll
        for (int o = 4; o > 0; o >>= 1) t = fmaxf(t, __shfl_xor_sync(0xffffffffu, t, o));
        if (tid == 0) sh[0] = t;
    }
    __syncthreads();
    mx = sh[0];
    __syncthreads();

    float sum = 0.f;
    #pragma unroll
    for (int u = 0; u < 5; u++) { v[u] = __expf(v[u] - mx); sum += v[u]; }
    #pragma unroll
    for (int o = 16; o > 0; o >>= 1) sum += __shfl_xor_sync(0xffffffffu, sum, o);
    if ((tid & 31) == 0) sh[tid >> 5] = sum;
    __syncthreads();
    if (tid < 32) {
        float t = (tid < 8) ? sh[tid] : 0.f;
        #pragma unroll
        for (int o = 4; o > 0; o >>= 1) t += __shfl_xor_sync(0xffffffffu, t, o);
        if (tid == 0) sh[0] = t;
    }
    __syncthreads();
    const float inv = 1.0f / sh[0];
    #pragma unroll
    for (int u = 0; u < 5; u++) {
        size_t o = (size_t)row * Sv + tid + u * 256;
        float p = v[u] * inv;
        float hi = tf32r(p);
        aH[o] = hi;
        aL[o] = tf32r(p - hi);
        if (relF) relF[o] = p;
    }
}

// ---------------- LayerNorm statistics + finalize ----------------
__global__ void zero_stats_kernel()
{
    int i = threadIdx.x;
    if (i < Bv * 2) g_stats[i] = 0.0;
}

__global__ __launch_bounds__(256)
void reduce_stats_kernel(const float* __restrict__ agg)
{
    const int b = blockIdx.y;
    const float* p = agg + (size_t)b * Sv * Cv;
    double s = 0.0, q = 0.0;
    for (int i = blockIdx.x * blockDim.x + threadIdx.x; i < Sv * Cv; i += gridDim.x * blockDim.x) {
        float v = p[i];
        s += (double)v;
        q += (double)v * (double)v;
    }
    #pragma unroll
    for (int o = 16; o > 0; o >>= 1) {
        s += __shfl_xor_sync(0xffffffffu, s, o);
        q += __shfl_xor_sync(0xffffffffu, q, o);
    }
    __shared__ double shs[8], shq[8];
    const int tid = threadIdx.x;
    if ((tid & 31) == 0) { shs[tid >> 5] = s; shq[tid >> 5] = q; }
    __syncthreads();
    if (tid == 0) {
        for (int w = 1; w < 8; w++) { s += shs[w]; q += shq[w]; }
        atomicAdd(&g_stats[b * 2 + 0], s);
        atomicAdd(&g_stats[b * 2 + 1], q);
    }
}

__global__ void mustd_kernel()
{
    int b = threadIdx.x;
    if (b < Bv) {
        const double n = (double)Sv * (double)Cv;
        double mu = g_stats[b * 2 + 0] / n;
        double var = g_stats[b * 2 + 1] / n - mu * mu;
        g_mu[b] = (float)mu;
        g_rstd[b] = rsqrtf((float)var + 1e-5f);
    }
}

__global__ __launch_bounds__(256)
void finalize_kernel(const float* __restrict__ agg, const float* __restrict__ lns,
                     const float* __restrict__ lnb, float* __restrict__ out, int accumulate)
{
    size_t idx = (size_t)blockIdx.x * blockDim.x + threadIdx.x;
    if (idx >= (size_t)Bv * Sv * Cv) return;
    int b = (int)(idx / ((size_t)Sv * Cv));
    int j = (int)(idx % ((size_t)Sv * Cv));
    float v = (agg[idx] - g_mu[b]) * g_rstd[b] * lns[j] + lnb[j];
    v = fmaxf(v, 0.f);
    out[idx] = accumulate ? out[idx] + v : v;
}

// ---------------- launch ----------------
extern "C" void kernel_launch(void* const* d_in, const int* in_sizes, int n_in,
                              void* d_out, int out_size)
{
    const float* x   = (const float*)d_in[0];
    const float* box = (const float*)d_in[1];
    const float* Wt  = (const float*)d_in[2];
    const float* bt  = (const float*)d_in[3];
    const float* Wp  = (const float*)d_in[4];
    const float* bp  = (const float*)d_in[5];
    const float* Wg  = (const float*)d_in[6];
    const float* lns = (const float*)d_in[7];
    const float* lnb = (const float*)d_in[8];
    const void*  owp = (n_in > 10) ? d_in[10] : nullptr;

    float* out = (float*)d_out;
    float* rel = out + (size_t)Bv * Sv * Cv;

    float *xh, *xl, *xth, *xtl, *wth, *wtl, *wph, *wpl, *wgh, *wgl;
    float *thh, *thl, *phh, *phl, *sim, *ath, *atl, *tph, *tpl, *agg;
    cudaGetSymbolAddress((void**)&xh,  g_xh);  cudaGetSymbolAddress((void**)&xl,  g_xl);
    cudaGetSymbolAddress((void**)&xth, g_xth); cudaGetSymbolAddress((void**)&xtl, g_xtl);
    cudaGetSymbolAddress((void**)&wth, g_wth); cudaGetSymbolAddress((void**)&wtl, g_wtl);
    cudaGetSymbolAddress((void**)&wph, g_wph); cudaGetSymbolAddress((void**)&wpl, g_wpl);
    cudaGetSymbolAddress((void**)&wgh, g_wgh); cudaGetSymbolAddress((void**)&wgl, g_wgl);
    cudaGetSymbolAddress((void**)&thh, g_thh); cudaGetSymbolAddress((void**)&thl, g_thl);
    cudaGetSymbolAddress((void**)&phh, g_phh); cudaGetSymbolAddress((void**)&phl, g_phl);
    cudaGetSymbolAddress((void**)&sim, g_sim);
    cudaGetSymbolAddress((void**)&ath, g_ath); cudaGetSymbolAddress((void**)&atl, g_atl);
    cudaGetSymbolAddress((void**)&tph, g_tph); cudaGetSymbolAddress((void**)&tpl, g_tpl);
    cudaGetSymbolAddress((void**)&agg, g_agg);

    cudaFuncSetAttribute(tcgemm, cudaFuncAttributeMaxDynamicSharedMemorySize, DYN_BYTES);

    const size_t sSC = (size_t)Sv * Cv;
    const size_t sSS = (size_t)Sv * Sv;
    const size_t sCC = (size_t)Cv * Cv;
    const float inv_sqrt = 0.04419417382415922f;
    const int NOSPLIT = 1 << 30;

    pos_kernel<<<(Bv * Sv + 255) / 256, 256>>>(box);
    // x: split + transpose (xT [B,C,S])
    conv_t_kernel<<<dim3(Cv / 32, Sv / 32, Bv), dim3(32, 8)>>>(x, xth, xtl, xh, xl, Sv, Cv);
    // weights: transpose to [n,k] + split
    conv_t_kernel<<<dim3(Cv / 32, Cv / 32, NGv), dim3(32, 8)>>>(Wt, wth, wtl, nullptr, nullptr, Cv, Cv);
    conv_t_kernel<<<dim3(Cv / 32, Cv / 32, NGv), dim3(32, 8)>>>(Wp, wph, wpl, nullptr, nullptr, Cv, Cv);
    conv_t_kernel<<<dim3(Cv / 32, Cv / 32, NGv), dim3(32, 8)>>>(Wg, wgh, wgl, nullptr, nullptr, Cv, Cv);

    for (int i = 0; i < NGv; i++) {
        // theta & phi (merged): [S,C] = x @ W^T' + b   (z<8 -> theta, z>=8 -> phi)
        tcgemm<<<dim3(2, 10, 16), 160, DYN_BYTES>>>(
            xh, xl, sSC, Cv,
            wth + i * sCC, wtl + i * sCC, wph + i * sCC, wpl + i * sCC, 0, Cv,
            nullptr, thh, thl, phh, phl, sSC, Cv,
            bt + (size_t)i * Cv, bp + (size_t)i * Cv, 1.0f, Cv, 8);

        // sim = theta @ phi^T * inv_sqrt   [S,S]
        tcgemm<<<dim3(5, 10, 8), 160, DYN_BYTES>>>(
            thh, thl, sSC, Cv,
            phh, phl, nullptr, nullptr, sSC, Cv,
            sim, nullptr, nullptr, nullptr, nullptr, sSS, Sv,
            nullptr, nullptr, inv_sqrt, Cv, NOSPLIT);

        // masked softmax -> attn hi/lo (+ relation_graph fp32 on last i)
        masked_softmax_kernel<<<Bv * Sv, 256>>>(sim, ath, atl, (i == NGv - 1) ? rel : nullptr, owp);

        // tmp = attn @ x   ( = attn @ (x^T)^T )   [S,C]
        tcgemm<<<dim3(2, 10, 8), 160, DYN_BYTES>>>(
            ath, atl, sSS, Sv,
            xth, xtl, nullptr, nullptr, (size_t)Cv * Sv, Sv,
            nullptr, tph, tpl, nullptr, nullptr, sSC, Cv,
            nullptr, nullptr, 1.0f, Sv, NOSPLIT);

        // agg = tmp @ W_gcn   [S,C]
        tcgemm<<<dim3(2, 10, 8), 160, DYN_BYTES>>>(
            tph, tpl, sSC, Cv,
            wgh + i * sCC, wgl + i * sCC, nullptr, nullptr, 0, Cv,
            agg, nullptr, nullptr, nullptr, nullptr, sSC, Cv,
            nullptr, nullptr, 1.0f, Cv, NOSPLIT);

        // LayerNorm over [S,C] per batch, out += relu(...)
        zero_stats_kernel<<<1, 32>>>();
        reduce_stats_kernel<<<dim3(64, Bv), 256>>>(agg);
        mustd_kernel<<<1, 32>>>();
        finalize_kernel<<<(int)((sSC * Bv + 255) / 256), 256>>>(
            agg, lns + (size_t)i * sSC, lnb + (size_t)i * sSC, out, i == 0 ? 0 : 1);
    }
}

// round 6
// speedup vs baseline: 5.2986x; 1.4401x over previous
#include <cuda_runtime.h>
#include <cuda_bf16.h>
#include <math.h>
#include <stdint.h>

#define NGv 12
#define Bv  8
#define Sv  1280
#define Cv  512

typedef __nv_bfloat16 bf16;

// ---------------- device scratch ----------------
__device__ bf16  g_xh [Bv*Sv*Cv], g_xl [Bv*Sv*Cv];     // x hi/lo [B,S,C]
__device__ bf16  g_xth[Bv*Cv*Sv], g_xtl[Bv*Cv*Sv];     // x^T hi/lo [B,C,S]
__device__ bf16  g_wth[NGv*Cv*Cv], g_wtl[NGv*Cv*Cv];   // W_theta^T hi/lo [NG,n,k]
__device__ bf16  g_wph[NGv*Cv*Cv], g_wpl[NGv*Cv*Cv];
__device__ bf16  g_wgh[NGv*Cv*Cv], g_wgl[NGv*Cv*Cv];
__device__ bf16  g_thh[Bv*Sv*Cv], g_thl[Bv*Sv*Cv];     // theta hi/lo
__device__ bf16  g_phh[Bv*Sv*Cv], g_phl[Bv*Sv*Cv];     // phi hi/lo
__device__ float g_sim[Bv*Sv*Sv];                      // sim fp32
__device__ bf16  g_ath[Bv*Sv*Sv], g_atl[Bv*Sv*Sv];     // attn hi/lo
__device__ bf16  g_tph[Bv*Sv*Cv], g_tpl[Bv*Sv*Cv];     // tmp hi/lo
__device__ float g_agg[Bv*Sv*Cv];
__device__ float g_cx[Bv*Sv], g_cy[Bv*Sv], g_rr[Bv*Sv];
__device__ double g_stats[Bv*2];
__device__ float g_mu[Bv], g_rstd[Bv];

// ---------------- helpers ----------------
__device__ __forceinline__ uint32_t sm2u(const void* p) {
    uint32_t a;
    asm("{ .reg .u64 t; cvta.to.shared.u64 t, %1; cvt.u32.u64 %0, t; }" : "=r"(a) : "l"(p));
    return a;
}
#define SWZ(o) ((o) ^ (((o) >> 3) & 0x70u))

__device__ __forceinline__ void bsplit(float x, bf16& h, bf16& l) {
    h = __float2bfloat16(x);
    l = __float2bfloat16(x - __bfloat162float(h));
}

__device__ __forceinline__ void cpasync16(uint32_t dst, const void* src) {
    asm volatile("cp.async.cg.shared.global [%0], [%1], 16;" :: "r"(dst), "l"(src));
}
// .noinc is load-bearing (R4 deadlock otherwise).
__device__ __forceinline__ void cpasync_arrive_noinc(uint32_t bar) {
    asm volatile("cp.async.mbarrier.arrive.noinc.shared.b64 [%0];" :: "r"(bar));
}
__device__ __forceinline__ void mbar_init(uint32_t bar, uint32_t cnt) {
    asm volatile("mbarrier.init.shared.b64 [%0], %1;" :: "r"(bar), "r"(cnt) : "memory");
}
__device__ __forceinline__ void mbar_wait(uint32_t bar, uint32_t parity) {
    asm volatile(
        "{\n\t"
        ".reg .pred P;\n\t"
        "WL%=:\n\t"
        "mbarrier.try_wait.parity.acquire.cta.shared::cta.b64 P, [%0], %1;\n\t"
        "@P bra WD%=;\n\t"
        "bra WL%=;\n\t"
        "WD%=:\n\t"
        "}"
        :: "r"(bar), "r"(parity) : "memory");
}
__device__ __forceinline__ void fence_proxy_async_cta() {
    asm volatile("fence.proxy.async.shared::cta;" ::: "memory");
}

#if defined(__CUDA_ARCH_FEAT_SM103_ALL) || !defined(__CUDA_ARCH__)
#define HAS_TCGEN05 1
#else
#define HAS_TCGEN05 0
#endif

#if HAS_TCGEN05
__device__ __forceinline__ void tc_commit(uint32_t bar) {
    asm volatile("tcgen05.commit.cta_group::1.mbarrier::arrive::one.shared::cluster.b64 [%0];"
                 :: "r"(bar) : "memory");
}
__device__ __forceinline__ void mma_bf16(uint32_t d, uint64_t ad, uint64_t bd, uint32_t idesc, bool acc) {
    uint32_t e = acc ? 1u : 0u;
    asm volatile(
        "{\n\t"
        ".reg .pred p;\n\t"
        "setp.ne.u32 p, %4, 0;\n\t"
        "tcgen05.mma.cta_group::1.kind::f16 [%0], %1, %2, %3, p;\n\t"
        "}"
        :: "r"(d), "l"(ad), "l"(bd), "r"(idesc), "r"(e) : "memory");
}
#define TC_ALLOC(smemaddr, n) \
    asm volatile("tcgen05.alloc.cta_group::1.sync.aligned.shared::cta.b32 [%0], %1;" \
                 :: "r"(smemaddr), "r"((uint32_t)(n)) : "memory")
#define TC_RELINQ() \
    asm volatile("tcgen05.relinquish_alloc_permit.cta_group::1.sync.aligned;")
#define TC_DEALLOC(tm, n) \
    asm volatile("tcgen05.dealloc.cta_group::1.sync.aligned.b32 %0, %1;" :: "r"(tm), "r"((uint32_t)(n)))
#define TC_FENCE_AFTER()  asm volatile("tcgen05.fence::after_thread_sync;" ::: "memory")
#define TC_WAIT_LD()      asm volatile("tcgen05.wait::ld.sync.aligned;" ::: "memory")
#define LDTM32(r, a) \
    asm volatile( \
        "tcgen05.ld.sync.aligned.32x32b.x32.b32 " \
        "{%0, %1, %2, %3, %4, %5, %6, %7, " \
        " %8, %9, %10, %11, %12, %13, %14, %15, " \
        " %16, %17, %18, %19, %20, %21, %22, %23, " \
        " %24, %25, %26, %27, %28, %29, %30, %31}, [%32];" \
        : "=r"((r)[0]),  "=r"((r)[1]),  "=r"((r)[2]),  "=r"((r)[3]), \
          "=r"((r)[4]),  "=r"((r)[5]),  "=r"((r)[6]),  "=r"((r)[7]), \
          "=r"((r)[8]),  "=r"((r)[9]),  "=r"((r)[10]), "=r"((r)[11]), \
          "=r"((r)[12]), "=r"((r)[13]), "=r"((r)[14]), "=r"((r)[15]), \
          "=r"((r)[16]), "=r"((r)[17]), "=r"((r)[18]), "=r"((r)[19]), \
          "=r"((r)[20]), "=r"((r)[21]), "=r"((r)[22]), "=r"((r)[23]), \
          "=r"((r)[24]), "=r"((r)[25]), "=r"((r)[26]), "=r"((r)[27]), \
          "=r"((r)[28]), "=r"((r)[29]), "=r"((r)[30]), "=r"((r)[31]) \
        : "r"(a))
#endif

static constexpr uint64_t DESC_BASE =
    (2ull << 61) | (1ull << 46) | (64ull << 32) | (1ull << 16);   // SW128, Blackwell, SBO=64, LBO=1
__device__ __forceinline__ uint64_t mk_desc(uint32_t addr) {
    return DESC_BASE | ((uint64_t)(addr >> 4) & 0x3FFFull);
}

// idesc (kind::f16): dtype=F32(1<<4), atype=BF16(1<<7), btype=BF16(1<<10), N=256 (32<<17), M=128 (8<<24)
static constexpr uint32_t IDESC_BF = (1u << 4) | (1u << 7) | (1u << 10) | (32u << 17) | (8u << 24);

// ---------------- tcgen05 3xBF16 GEMM: D = alpha*(A @ B^T) + bias ----------------
// A[M,K] K-major bf16 hi/lo, B[N,K] K-major bf16 hi/lo. Tile 128x256, K-chunk 64 (128B rows).
// outF -> fp32; outH/outL -> bf16 hi/lo split.
#define KC 64
#define STG_BYTES 98304          // 96KB/stage: Ah 16K | Al 16K | Bh 32K | Bl 32K
#define OFF_AL 16384
#define OFF_BH 32768
#define OFF_BL 65536
#define DYN_BYTES 196608

__global__ __launch_bounds__(160, 1)
void tcgemm(const bf16* __restrict__ Ah, const bf16* __restrict__ Al, size_t sAz, int ldA,
            const bf16* __restrict__ Bh, const bf16* __restrict__ Bl,
            const bf16* __restrict__ Bh2, const bf16* __restrict__ Bl2, size_t sBz, int ldB,
            float* outF, bf16* outH, bf16* outL, bf16* outH2, bf16* outL2,
            size_t sOz, int ldO,
            const float* bias, const float* bias2, float alpha, int K, int zsplit)
{
#if HAS_TCGEN05
    extern __shared__ __align__(1024) char dynsm[];
    __shared__ __align__(8) uint64_t s_full[2], s_empty[2], s_done;
    __shared__ uint32_t s_tptr;

    const int tid = threadIdx.x;
    const int wid = tid >> 5;
    const int lane = tid & 31;

    int z = blockIdx.z;
    if (z >= zsplit) { z -= zsplit; Bh = Bh2; Bl = Bl2; outH = outH2; outL = outL2; bias = bias2; }
    const int m0   = blockIdx.y * 128;
    const int col0 = blockIdx.x * 256;

    const uint32_t dynu = sm2u(dynsm);
    uint32_t fullb[2]  = { sm2u(&s_full[0]),  sm2u(&s_full[1])  };
    uint32_t emptyb[2] = { sm2u(&s_empty[0]), sm2u(&s_empty[1]) };
    const uint32_t doneb = sm2u(&s_done);

    if (tid == 0) {
        mbar_init(fullb[0], 128); mbar_init(fullb[1], 128);
        mbar_init(emptyb[0], 1);  mbar_init(emptyb[1], 1);
        mbar_init(doneb, 1);
    }
    __syncthreads();
    if (wid == 4) {
        TC_ALLOC(sm2u(&s_tptr), 256);
        TC_RELINQ();
    }
    __syncthreads();
    const uint32_t tmem = s_tptr;

    const int nk = K / KC;

    if (wid < 4) {
        // ---- producers (128 threads), 16B = 8 bf16 per cp.async ----
        const bf16* aH = Ah + (size_t)z * sAz + (size_t)m0 * ldA;
        const bf16* aL = Al + (size_t)z * sAz + (size_t)m0 * ldA;
        const bf16* bH = Bh + (size_t)z * sBz + (size_t)col0 * ldB;
        const bf16* bL = Bl + (size_t)z * sBz + (size_t)col0 * ldB;
        int st = 0, ph = 1;
        for (int c = 0; c < nk; c++) {
            mbar_wait(emptyb[st], ph);
            const uint32_t sb = dynu + st * STG_BYTES;
            const int k0 = c * KC;
            // A tiles: 128 rows x 128B = 1024 float4 each (hi, lo)
            #pragma unroll
            for (int i = 0; i < 8; i++) {
                int idx = i * 128 + tid;
                int r = idx >> 3, cc = idx & 7;
                uint32_t so = SWZ((uint32_t)(r * 128 + cc * 16));
                const size_t go = (size_t)r * ldA + k0 + cc * 8;
                cpasync16(sb + so, aH + go);
                cpasync16(sb + OFF_AL + so, aL + go);
            }
            // B tiles: 256 rows x 128B = 2048 float4 each (hi, lo)
            #pragma unroll
            for (int i = 0; i < 16; i++) {
                int idx = i * 128 + tid;
                int r = idx >> 3, cc = idx & 7;
                uint32_t so = SWZ((uint32_t)(r * 128 + cc * 16));
                const size_t go = (size_t)r * ldB + k0 + cc * 8;
                cpasync16(sb + OFF_BH + so, bH + go);
                cpasync16(sb + OFF_BL + so, bL + go);
            }
            cpasync_arrive_noinc(fullb[st]);
            if (++st == 2) { st = 0; ph ^= 1; }
        }
    } else if (lane == 0) {
        // ---- MMA issuer: 4 K-steps (16 bf16 each) x {hh, hl, lh} per chunk ----
        int st = 0, ph = 0;
        for (int c = 0; c < nk; c++) {
            mbar_wait(fullb[st], ph);
            fence_proxy_async_cta();
            const uint32_t sb = dynu + st * STG_BYTES;
            uint64_t dah = mk_desc(sb),          dal = mk_desc(sb + OFF_AL);
            uint64_t dbh = mk_desc(sb + OFF_BH), dbl = mk_desc(sb + OFF_BL);
            #pragma unroll
            for (int ks = 0; ks < 4; ks++)
                mma_bf16(tmem, dah + ks * 2, dbh + ks * 2, IDESC_BF, !(c == 0 && ks == 0));
            #pragma unroll
            for (int ks = 0; ks < 4; ks++)
                mma_bf16(tmem, dah + ks * 2, dbl + ks * 2, IDESC_BF, true);
            #pragma unroll
            for (int ks = 0; ks < 4; ks++)
                mma_bf16(tmem, dal + ks * 2, dbh + ks * 2, IDESC_BF, true);
            tc_commit(emptyb[st]);
            if (++st == 2) { st = 0; ph ^= 1; }
        }
        tc_commit(doneb);
    }

    mbar_wait(doneb, 0);
    TC_FENCE_AFTER();

    if (wid < 4) {
        float* tile = (float*)(dynsm + wid * 4352);     // 32x33 floats per warp
        const size_t obase = (size_t)z * sOz;
        for (int c0 = 0; c0 < 256; c0 += 32) {
            uint32_t regs[32];
            LDTM32(regs, tmem + c0);
            TC_WAIT_LD();
            #pragma unroll
            for (int j = 0; j < 32; j++) {
                float v = __uint_as_float(regs[j]) * alpha;
                if (bias) v += bias[col0 + c0 + j];
                tile[lane * 33 + j] = v;
            }
            __syncwarp();
            #pragma unroll
            for (int i = 0; i < 8; i++) {
                int f = i * 32 + lane;
                int rr = f >> 3, q = (f & 7) * 4;
                float vv[4];
                vv[0] = tile[rr * 33 + q + 0];
                vv[1] = tile[rr * 33 + q + 1];
                vv[2] = tile[rr * 33 + q + 2];
                vv[3] = tile[rr * 33 + q + 3];
                size_t off = obase + (size_t)(m0 + wid * 32 + rr) * ldO + col0 + c0 + q;
                if (outF) {
                    float4 o4 = { vv[0], vv[1], vv[2], vv[3] };
                    *(float4*)(outF + off) = o4;
                }
                if (outH) {
                    uint32_t hw[4], lw[4];
                    #pragma unroll
                    for (int t = 0; t < 4; t++) {
                        bf16 h, l;
                        bsplit(vv[t], h, l);
                        hw[t] = (uint32_t)__bfloat16_as_ushort(h);
                        lw[t] = (uint32_t)__bfloat16_as_ushort(l);
                    }
                    uint2 uh = { hw[0] | (hw[1] << 16), hw[2] | (hw[3] << 16) };
                    uint2 ul = { lw[0] | (lw[1] << 16), lw[2] | (lw[3] << 16) };
                    *(uint2*)(outH + off) = uh;
                    *(uint2*)(outL + off) = ul;
                }
            }
            __syncwarp();
        }
    }
    __syncthreads();
    if (wid == 4) TC_DEALLOC(tmem, 256);
#else
    // -------- plain-sm_103 fallback --------
    int z = blockIdx.z;
    if (z >= zsplit) { z -= zsplit; Bh = Bh2; Bl = Bl2; outH = outH2; outL = outL2; bias = bias2; }
    const int m0   = blockIdx.y * 128;
    const int col0 = blockIdx.x * 256;
    const bf16* aH = Ah + (size_t)z * sAz;
    const bf16* aL = Al + (size_t)z * sAz;
    const bf16* bH = Bh + (size_t)z * sBz;
    const bf16* bL = Bl + (size_t)z * sBz;
    for (int idx = threadIdx.x; idx < 128 * 256; idx += blockDim.x) {
        int mi = m0 + (idx >> 8);
        int ni = col0 + (idx & 255);
        const bf16* pa  = aH + (size_t)mi * ldA;
        const bf16* pa2 = aL + (size_t)mi * ldA;
        const bf16* pb  = bH + (size_t)ni * ldB;
        const bf16* pb2 = bL + (size_t)ni * ldB;
        float s = 0.f;
        for (int k = 0; k < K; k++)
            s += (__bfloat162float(pa[k]) + __bfloat162float(pa2[k])) *
                 (__bfloat162float(pb[k]) + __bfloat162float(pb2[k]));
        float v = s * alpha + (bias ? bias[ni] : 0.f);
        size_t off = (size_t)z * sOz + (size_t)mi * ldO + ni;
        if (outF) outF[off] = v;
        if (outH) {
            bf16 h, l;
            bsplit(v, h, l);
            outH[off] = h;
            outL[off] = l;
        }
    }
#endif
}

// ---------------- transpose + bf16 hi/lo split ----------------
// in [Z,R,Cc] -> th/tl [Z,Cc,R] transposed split; sh/sl (optional) straight split.
__global__ void conv_t_kernel(const float* __restrict__ in, bf16* __restrict__ th,
                              bf16* __restrict__ tl, bf16* sh, bf16* sl, int R, int Cc)
{
    __shared__ float t[32][33];
    const int z = blockIdx.z;
    const size_t zb = (size_t)z * R * Cc;
    const int r0 = blockIdx.y * 32, c0 = blockIdx.x * 32;
    #pragma unroll
    for (int k = 0; k < 4; k++) {
        int r = r0 + threadIdx.y + k * 8;
        size_t idx = zb + (size_t)r * Cc + c0 + threadIdx.x;
        float v = in[idx];
        t[threadIdx.y + k * 8][threadIdx.x] = v;
        if (sh) {
            bf16 h, l;
            bsplit(v, h, l);
            sh[idx] = h;
            sl[idx] = l;
        }
    }
    __syncthreads();
    #pragma unroll
    for (int k = 0; k < 4; k++) {
        int cc = c0 + threadIdx.y + k * 8;
        int rr = r0 + threadIdx.x;
        float v = t[threadIdx.x][threadIdx.y + k * 8];
        size_t o = zb + (size_t)cc * R + rr;
        bf16 h, l;
        bsplit(v, h, l);
        th[o] = h;
        tl[o] = l;
    }
}

// ---------------- box centers ----------------
__global__ void pos_kernel(const float* __restrict__ box)
{
    int idx = blockIdx.x * blockDim.x + threadIdx.x;
    if (idx >= Bv * Sv) return;
    float cx = (box[idx * 4 + 0] + box[idx * 4 + 2]) * 0.5f;
    float cy = (box[idx * 4 + 1] + box[idx * 4 + 3]) * 0.5f;
    g_cx[idx] = cx; g_cy[idx] = cy; g_rr[idx] = cx * cx + cy * cy;
}

// ---------------- masked softmax -> bf16 hi/lo (+optional fp32 relation_graph) --------
__global__ __launch_bounds__(256)
void masked_softmax_kernel(const float* __restrict__ sim, bf16* __restrict__ aH,
                           bf16* __restrict__ aL, float* relF, const void* __restrict__ owp)
{
    const int row = blockIdx.x;
    const int b = row / Sv;
    const int tid = threadIdx.x;
    const float* srow = sim + (size_t)row * Sv;

    float ow = 224.0f;
    if (owp) {
        int vi = *(const int*)owp;
        ow = (vi > 0 && vi < 1000000) ? (float)vi : __int_as_float(vi);
    }
    const float thr2 = (0.2f * ow) * (0.2f * ow);

    const float rn = g_rr[row], cxn = g_cx[row], cyn = g_cy[row];
    const float* cxb = g_cx + b * Sv;
    const float* cyb = g_cy + b * Sv;
    const float* rb  = g_rr + b * Sv;

    float v[5];
    float mx = -INFINITY;
    #pragma unroll
    for (int u = 0; u < 5; u++) {
        int m = tid + u * 256;
        float d2 = (rn - 2.0f * (cxn * cxb[m] + cyn * cyb[m])) + rb[m];
        v[u] = (d2 > thr2) ? -INFINITY : srow[m];
        mx = fmaxf(mx, v[u]);
    }

    __shared__ float sh[8];
    #pragma unroll
    for (int o = 16; o > 0; o >>= 1) mx = fmaxf(mx, __shfl_xor_sync(0xffffffffu, mx, o));
    if ((tid & 31) == 0) sh[tid >> 5] = mx;
    __syncthreads();
    if (tid < 32) {
        float t = (tid < 8) ? sh[tid] : -INFINITY;
        #pragma unroll
        for (int o = 4; o > 0; o >>= 1) t = fmaxf(t, __shfl_xor_sync(0xffffffffu, t, o));
        if (tid == 0) sh[0] = t;
    }
    __syncthreads();
    mx = sh[0];
    __syncthreads();

    float sum = 0.f;
    #pragma unroll
    for (int u = 0; u < 5; u++) { v[u] = __expf(v[u] - mx); sum += v[u]; }
    #pragma unroll
    for (int o = 16; o > 0; o >>= 1) sum += __shfl_xor_sync(0xffffffffu, sum, o);
    if ((tid & 31) == 0) sh[tid >> 5] = sum;
    __syncthreads();
    if (tid < 32) {
        float t = (tid < 8) ? sh[tid] : 0.f;
        #pragma unroll
        for (int o = 4; o > 0; o >>= 1) t += __shfl_xor_sync(0xffffffffu, t, o);
        if (tid == 0) sh[0] = t;
    }
    __syncthreads();
    const float inv = 1.0f / sh[0];
    #pragma unroll
    for (int u = 0; u < 5; u++) {
        size_t o = (size_t)row * Sv + tid + u * 256;
        float p = v[u] * inv;
        bf16 h, l;
        bsplit(p, h, l);
        aH[o] = h;
        aL[o] = l;
        if (relF) relF[o] = p;
    }
}

// ---------------- LayerNorm statistics + finalize ----------------
__global__ void zero_stats_kernel()
{
    int i = threadIdx.x;
    if (i < Bv * 2) g_stats[i] = 0.0;
}

__global__ __launch_bounds__(256)
void reduce_stats_kernel(const float* __restrict__ agg)
{
    const int b = blockIdx.y;
    const float* p = agg + (size_t)b * Sv * Cv;
    double s = 0.0, q = 0.0;
    for (int i = blockIdx.x * blockDim.x + threadIdx.x; i < Sv * Cv; i += gridDim.x * blockDim.x) {
        float v = p[i];
        s += (double)v;
        q += (double)v * (double)v;
    }
    #pragma unroll
    for (int o = 16; o > 0; o >>= 1) {
        s += __shfl_xor_sync(0xffffffffu, s, o);
        q += __shfl_xor_sync(0xffffffffu, q, o);
    }
    __shared__ double shs[8], shq[8];
    const int tid = threadIdx.x;
    if ((tid & 31) == 0) { shs[tid >> 5] = s; shq[tid >> 5] = q; }
    __syncthreads();
    if (tid == 0) {
        for (int w = 1; w < 8; w++) { s += shs[w]; q += shq[w]; }
        atomicAdd(&g_stats[b * 2 + 0], s);
        atomicAdd(&g_stats[b * 2 + 1], q);
    }
}

__global__ void mustd_kernel()
{
    int b = threadIdx.x;
    if (b < Bv) {
        const double n = (double)Sv * (double)Cv;
        double mu = g_stats[b * 2 + 0] / n;
        double var = g_stats[b * 2 + 1] / n - mu * mu;
        g_mu[b] = (float)mu;
        g_rstd[b] = rsqrtf((float)var + 1e-5f);
    }
}

__global__ __launch_bounds__(256)
void finalize_kernel(const float* __restrict__ agg, const float* __restrict__ lns,
                     const float* __restrict__ lnb, float* __restrict__ out, int accumulate)
{
    size_t idx = (size_t)blockIdx.x * blockDim.x + threadIdx.x;
    if (idx >= (size_t)Bv * Sv * Cv) return;
    int b = (int)(idx / ((size_t)Sv * Cv));
    int j = (int)(idx % ((size_t)Sv * Cv));
    float v = (agg[idx] - g_mu[b]) * g_rstd[b] * lns[j] + lnb[j];
    v = fmaxf(v, 0.f);
    out[idx] = accumulate ? out[idx] + v : v;
}

// ---------------- launch ----------------
extern "C" void kernel_launch(void* const* d_in, const int* in_sizes, int n_in,
                              void* d_out, int out_size)
{
    const float* x   = (const float*)d_in[0];
    const float* box = (const float*)d_in[1];
    const float* Wt  = (const float*)d_in[2];
    const float* bt  = (const float*)d_in[3];
    const float* Wp  = (const float*)d_in[4];
    const float* bp  = (const float*)d_in[5];
    const float* Wg  = (const float*)d_in[6];
    const float* lns = (const float*)d_in[7];
    const float* lnb = (const float*)d_in[8];
    const void*  owp = (n_in > 10) ? d_in[10] : nullptr;

    float* out = (float*)d_out;
    float* rel = out + (size_t)Bv * Sv * Cv;

    bf16 *xh, *xl, *xth, *xtl, *wth, *wtl, *wph, *wpl, *wgh, *wgl;
    bf16 *thh, *thl, *phh, *phl, *ath, *atl, *tph, *tpl;
    float *sim, *agg;
    cudaGetSymbolAddress((void**)&xh,  g_xh);  cudaGetSymbolAddress((void**)&xl,  g_xl);
    cudaGetSymbolAddress((void**)&xth, g_xth); cudaGetSymbolAddress((void**)&xtl, g_xtl);
    cudaGetSymbolAddress((void**)&wth, g_wth); cudaGetSymbolAddress((void**)&wtl, g_wtl);
    cudaGetSymbolAddress((void**)&wph, g_wph); cudaGetSymbolAddress((void**)&wpl, g_wpl);
    cudaGetSymbolAddress((void**)&wgh, g_wgh); cudaGetSymbolAddress((void**)&wgl, g_wgl);
    cudaGetSymbolAddress((void**)&thh, g_thh); cudaGetSymbolAddress((void**)&thl, g_thl);
    cudaGetSymbolAddress((void**)&phh, g_phh); cudaGetSymbolAddress((void**)&phl, g_phl);
    cudaGetSymbolAddress((void**)&sim, g_sim);
    cudaGetSymbolAddress((void**)&ath, g_ath); cudaGetSymbolAddress((void**)&atl, g_atl);
    cudaGetSymbolAddress((void**)&tph, g_tph); cudaGetSymbolAddress((void**)&tpl, g_tpl);
    cudaGetSymbolAddress((void**)&agg, g_agg);

    cudaFuncSetAttribute(tcgemm, cudaFuncAttributeMaxDynamicSharedMemorySize, DYN_BYTES);

    const size_t sSC = (size_t)Sv * Cv;
    const size_t sSS = (size_t)Sv * Sv;
    const size_t sCC = (size_t)Cv * Cv;
    const float inv_sqrt = 0.04419417382415922f;
    const int NOSPLIT = 1 << 30;

    pos_kernel<<<(Bv * Sv + 255) / 256, 256>>>(box);
    // x: split + transpose
    conv_t_kernel<<<dim3(Cv / 32, Sv / 32, Bv), dim3(32, 8)>>>(x, xth, xtl, xh, xl, Sv, Cv);
    // weights: transpose to [n,k] + split
    conv_t_kernel<<<dim3(Cv / 32, Cv / 32, NGv), dim3(32, 8)>>>(Wt, wth, wtl, nullptr, nullptr, Cv, Cv);
    conv_t_kernel<<<dim3(Cv / 32, Cv / 32, NGv), dim3(32, 8)>>>(Wp, wph, wpl, nullptr, nullptr, Cv, Cv);
    conv_t_kernel<<<dim3(Cv / 32, Cv / 32, NGv), dim3(32, 8)>>>(Wg, wgh, wgl, nullptr, nullptr, Cv, Cv);

    for (int i = 0; i < NGv; i++) {
        // theta & phi merged: z<8 -> theta, z>=8 -> phi
        tcgemm<<<dim3(2, 10, 16), 160, DYN_BYTES>>>(
            xh, xl, sSC, Cv,
            wth + i * sCC, wtl + i * sCC, wph + i * sCC, wpl + i * sCC, 0, Cv,
            nullptr, thh, thl, phh, phl, sSC, Cv,
            bt + (size_t)i * Cv, bp + (size_t)i * Cv, 1.0f, Cv, 8);

        // sim = theta @ phi^T * inv_sqrt
        tcgemm<<<dim3(5, 10, 8), 160, DYN_BYTES>>>(
            thh, thl, sSC, Cv,
            phh, phl, nullptr, nullptr, sSC, Cv,
            sim, nullptr, nullptr, nullptr, nullptr, sSS, Sv,
            nullptr, nullptr, inv_sqrt, Cv, NOSPLIT);

        // masked softmax -> attn hi/lo (+ rel fp32 on last i)
        masked_softmax_kernel<<<Bv * Sv, 256>>>(sim, ath, atl, (i == NGv - 1) ? rel : nullptr, owp);

        // tmp = attn @ x
        tcgemm<<<dim3(2, 10, 8), 160, DYN_BYTES>>>(
            ath, atl, sSS, Sv,
            xth, xtl, nullptr, nullptr, (size_t)Cv * Sv, Sv,
            nullptr, tph, tpl, nullptr, nullptr, sSC, Cv,
            nullptr, nullptr, 1.0f, Sv, NOSPLIT);

        // agg = tmp @ W_gcn
        tcgemm<<<dim3(2, 10, 8), 160, DYN_BYTES>>>(
            tph, tpl, sSC, Cv,
            wgh + i * sCC, wgl + i * sCC, nullptr, nullptr, 0, Cv,
            agg, nullptr, nullptr, nullptr, nullptr, sSC, Cv,
            nullptr, nullptr, 1.0f, Cv, NOSPLIT);

        // LayerNorm + out += relu(...)
        zero_stats_kernel<<<1, 32>>>();
        reduce_stats_kernel<<<dim3(64, Bv), 256>>>(agg);
        mustd_kernel<<<1, 32>>>();
        finalize_kernel<<<(int)((sSC * Bv + 255) / 256), 256>>>(
            agg, lns + (size_t)i * sSC, lnb + (size_t)i * sSC, out, i == 0 ? 0 : 1);
    }
}